// round 12
// baseline (speedup 1.0000x reference)
#include <cuda_runtime.h>
#include <math_constants.h>

#define BB   4
#define NP   2048
#define KNN  64
#define EPS  0.005f
#define LOG_MU (-7.6246190f)   /* -log(2048) */
#define NSEG 4                 /* row segments for the column pass */

/* ------------ scratch (no allocations allowed) ------------ */
__device__ float g_lu[BB*NP];
__device__ float g_lv[BB*NP];
__device__ float g_sin[BB*NP];
__device__ float g_spr[BB*NP];
__device__ int   g_assign[BB*NP];
__device__ float g_avg[BB*NP];
__device__ float g_pmx[BB][NSEG][NP];   /* column-pass partial max  */
__device__ float g_psm[BB][NSEG][NP];   /* column-pass partial sum  */
/* materialized logK = -C/eps : [b][n][m] — 67 MB */
__device__ float g_K [(size_t)BB*NP*NP];

/* TF32 rounding (cuBLAS/CUTLASS conversion path: round-nearest-ties-away) */
__device__ __forceinline__ float tf32r(float x)
{
    float r;
    asm("cvt.rna.tf32.f32 %0, %1;" : "=f"(r) : "f"(x));
    return r;
}

/* online branchy logsumexp update (fast exp) */
#define ONL(e, mx, s) \
    { if ((e) > (mx)) { (s) = fmaf((s), __expf((mx) - (e)), 1.f); (mx) = (e); } \
      else              (s) += __expf((e) - (mx)); }

/* ------------ threefry2x32, bit-exact vs JAX ------------ */
__device__ __forceinline__ void threefry2x32(unsigned k0, unsigned k1,
                                             unsigned &x0, unsigned &x1)
{
    unsigned ks2 = k0 ^ k1 ^ 0x1BD11BDAu;
    x0 += k0; x1 += k1;
#define TFR(r) { x0 += x1; x1 = (x1 << (r)) | (x1 >> (32 - (r))); x1 ^= x0; }
    TFR(13) TFR(15) TFR(26) TFR(6)
    x0 += k1;  x1 += ks2 + 1u;
    TFR(17) TFR(29) TFR(16) TFR(24)
    x0 += ks2; x1 += k0 + 2u;
    TFR(13) TFR(15) TFR(26) TFR(6)
    x0 += k0;  x1 += k1 + 3u;
    TFR(17) TFR(29) TFR(16) TFR(24)
    x0 += k1;  x1 += ks2 + 4u;
    TFR(13) TFR(15) TFR(26) TFR(6)
    x0 += ks2; x1 += k0 + 5u;
#undef TFR
}

/* ------------ init: squared norms (full fp32) + zero duals ------------ */
__global__ void init_kernel(const float* __restrict__ preds,
                            const float* __restrict__ inputs)
{
    int i = blockIdx.x * blockDim.x + threadIdx.x;
    if (i < BB*NP) {
        float x = inputs[3*i], y = inputs[3*i+1], z = inputs[3*i+2];
        g_sin[i] = fmaf(z, z, fmaf(y, y, x*x));
        x = preds[3*i]; y = preds[3*i+1]; z = preds[3*i+2];
        g_spr[i] = fmaf(z, z, fmaf(y, y, x*x));
        g_lu[i] = 0.f;
        g_lv[i] = 0.f;
    }
}

/* ------------ build logK: g_K[b][n][m], rows = inputs, cols = preds ------------ */
__global__ void __launch_bounds__(256) build_logK(
    const float* __restrict__ rowPts,
    const float* __restrict__ innerPts)
{
    __shared__ float4 shp[NP];
    int b = blockIdx.y;
    const float* ip = innerPts + b*NP*3;
    for (int i = threadIdx.x; i < NP; i += 256)
        shp[i] = make_float4(tf32r(ip[3*i]), tf32r(ip[3*i+1]), tf32r(ip[3*i+2]),
                             g_spr[b*NP + i]);
    __syncthreads();

    int warp = threadIdx.x >> 5, lane = threadIdx.x & 31;
    int row = blockIdx.x * 8 + warp;
    const float* rp = rowPts + (b*NP + row)*3;
    float ax = tf32r(rp[0]), ay = tf32r(rp[1]), az = tf32r(rp[2]);
    float sa = g_sin[b*NP + row];
    float* orow = g_K + ((size_t)b*NP + row) * NP;

    for (int m = lane; m < NP; m += 32) {
        float4 p = shp[m];
        float dot = fmaf(az, p.z, fmaf(ay, p.y, ax * p.x));
        float d2  = fmaxf(__fadd_rn(__fadd_rn(sa, p.w), -2.0f * dot), 0.f);
        orow[m] = -(d2 / EPS);
    }
}

/* merge NSEG column partials for column m -> lv value (colB algebra) */
__device__ __forceinline__ float merge_lv(int b, int m)
{
    float mx = -CUDART_INF_F, s = 0.f;
#pragma unroll
    for (int seg = 0; seg < NSEG; seg++) {
        float m2 = g_pmx[b][seg][m], s2 = g_psm[b][seg][m];
        float nm = fmaxf(mx, m2);
        s = s * __expf(mx - nm) + s2 * __expf(m2 - nm);
        mx = nm;
    }
    float r = __fadd_rn(logf(s), mx);
    return __fadd_rn(LOG_MU, -r);
}

/* ------------ row half-step (fused lv merge):
   lu[n] = LOG_MU - lse_m( g_K[n][m] + lv[m] )
   FIRST=1: lv read from g_lv (zeros); FIRST=0: lv merged from partials.
   1 warp per row, 8-wide batched global loads (MLP=8).                   */
template<int FIRST>
__global__ void __launch_bounds__(256) sinkhorn_row(void)
{
    __shared__ float shl[NP];
    int b = blockIdx.y;
    if (FIRST) {
        for (int i = threadIdx.x; i < NP; i += 256) shl[i] = g_lv[b*NP + i];
    } else {
        for (int i = threadIdx.x; i < NP; i += 256) shl[i] = merge_lv(b, i);
    }
    __syncthreads();

    int warp = threadIdx.x >> 5, lane = threadIdx.x & 31;
    int row = blockIdx.x * 8 + warp;
    const float4* M4 = (const float4*)(g_K + ((size_t)b*NP + row) * NP);
    const float4* L4 = (const float4*)shl;

    float mx0 = -CUDART_INF_F, mx1 = -CUDART_INF_F,
          mx2 = -CUDART_INF_F, mx3 = -CUDART_INF_F;
    float s0 = 0.f, s1 = 0.f, s2 = 0.f, s3 = 0.f;

#pragma unroll
    for (int ii = 0; ii < 16; ii += 8) {
        /* 8 independent global loads in flight */
        float4 k0 = M4[(ii+0)*32 + lane];
        float4 k1 = M4[(ii+1)*32 + lane];
        float4 k2 = M4[(ii+2)*32 + lane];
        float4 k3 = M4[(ii+3)*32 + lane];
        float4 k4 = M4[(ii+4)*32 + lane];
        float4 k5 = M4[(ii+5)*32 + lane];
        float4 k6 = M4[(ii+6)*32 + lane];
        float4 k7 = M4[(ii+7)*32 + lane];
        float4 l; float e;
#define ROWSTEP(kk, jj) \
        l = L4[(ii+jj)*32 + lane]; \
        e = __fadd_rn(kk.x, l.x); ONL(e, mx0, s0) \
        e = __fadd_rn(kk.y, l.y); ONL(e, mx1, s1) \
        e = __fadd_rn(kk.z, l.z); ONL(e, mx2, s2) \
        e = __fadd_rn(kk.w, l.w); ONL(e, mx3, s3)
        ROWSTEP(k0, 0) ROWSTEP(k1, 1) ROWSTEP(k2, 2) ROWSTEP(k3, 3)
        ROWSTEP(k4, 4) ROWSTEP(k5, 5) ROWSTEP(k6, 6) ROWSTEP(k7, 7)
#undef ROWSTEP
    }

    float nm, s, mx;
    nm = fmaxf(mx0, mx1); s0 = s0 * __expf(mx0 - nm) + s1 * __expf(mx1 - nm); mx0 = nm;
    nm = fmaxf(mx2, mx3); s2 = s2 * __expf(mx2 - nm) + s3 * __expf(mx3 - nm); mx2 = nm;
    nm = fmaxf(mx0, mx2); s  = s0 * __expf(mx0 - nm) + s2 * __expf(mx2 - nm); mx = nm;

#pragma unroll
    for (int off = 16; off; off >>= 1) {
        float om = __shfl_xor_sync(0xffffffffu, mx, off);
        float os = __shfl_xor_sync(0xffffffffu, s,  off);
        nm = fmaxf(mx, om);
        s  = s * __expf(mx - nm) + os * __expf(om - nm);
        mx = nm;
    }
    if (lane == 0) {
        float r = __fadd_rn(logf(s), mx);
        g_lu[b*NP + row] = __fadd_rn(LOG_MU, -r);
    }
}

/* ------------ column pass stage A: partial lse over a 32-col x 512-row tile.
   grid.x = 64 col-tiles * NSEG row-segments, grid.y = BB.
   256 threads = 8 col-threads (float4 = 4 cols) x 32 row-subgroups;
   each thread covers 16 rows with 8-wide batched loads (MLP=8).          */
__global__ void __launch_bounds__(256) sinkhorn_colA(void)
{
    __shared__ float shlu[512];
    __shared__ float smx[32][33], ssm[32][33];

    int b    = blockIdx.y;
    int seg  = blockIdx.x & (NSEG - 1);
    int tile = blockIdx.x >> 2;            /* 0..63 */
    int n0   = seg * 512;

    for (int i = threadIdx.x; i < 512; i += 256) shlu[i] = g_lu[b*NP + n0 + i];
    __syncthreads();

    int t = threadIdx.x;
    int u = t & 7, sg = t >> 3;
    int m0 = tile * 32;
    const float4* M4 = (const float4*)(g_K + (size_t)b*NP*NP + m0);

    float mxa = -CUDART_INF_F, mxb = -CUDART_INF_F,
          mxc = -CUDART_INF_F, mxd = -CUDART_INF_F;
    float sa = 0.f, sb = 0.f, sc = 0.f, sd = 0.f;

    {
        /* 8 independent strided loads in flight, twice */
#pragma unroll
        for (int half = 0; half < 2; half++) {
            int base = n0 + sg + 256*half;
            float4 v0 = M4[(size_t)(base + 32*0) * (NP/4) + u];
            float4 v1 = M4[(size_t)(base + 32*1) * (NP/4) + u];
            float4 v2 = M4[(size_t)(base + 32*2) * (NP/4) + u];
            float4 v3 = M4[(size_t)(base + 32*3) * (NP/4) + u];
            float4 v4 = M4[(size_t)(base + 32*4) * (NP/4) + u];
            float4 v5 = M4[(size_t)(base + 32*5) * (NP/4) + u];
            float4 v6 = M4[(size_t)(base + 32*6) * (NP/4) + u];
            float4 v7 = M4[(size_t)(base + 32*7) * (NP/4) + u];
            float lu_; float e;
#define COLSTEP(vv, jj) \
            lu_ = shlu[base - n0 + 32*jj]; \
            e = __fadd_rn(vv.x, lu_); ONL(e, mxa, sa) \
            e = __fadd_rn(vv.y, lu_); ONL(e, mxb, sb) \
            e = __fadd_rn(vv.z, lu_); ONL(e, mxc, sc) \
            e = __fadd_rn(vv.w, lu_); ONL(e, mxd, sd)
            COLSTEP(v0, 0) COLSTEP(v1, 1) COLSTEP(v2, 2) COLSTEP(v3, 3)
            COLSTEP(v4, 4) COLSTEP(v5, 5) COLSTEP(v6, 6) COLSTEP(v7, 7)
#undef COLSTEP
        }
    }
    smx[sg][4*u+0] = mxa; ssm[sg][4*u+0] = sa;
    smx[sg][4*u+1] = mxb; ssm[sg][4*u+1] = sb;
    smx[sg][4*u+2] = mxc; ssm[sg][4*u+2] = sc;
    smx[sg][4*u+3] = mxd; ssm[sg][4*u+3] = sd;
    __syncthreads();

    if (t < 32) {
        float mx = -CUDART_INF_F, s = 0.f;
#pragma unroll
        for (int g = 0; g < 32; g++) {
            float m2 = smx[g][t], s2 = ssm[g][t];
            float nm = fmaxf(mx, m2);
            s = s * __expf(mx - nm) + s2 * __expf(m2 - nm);
            mx = nm;
        }
        g_pmx[b][seg][m0 + t] = mx;
        g_psm[b][seg][m0 + t] = s;
    }
}

/* ------------ column pass stage B (once, before assign): merge -> g_lv ------------ */
__global__ void __launch_bounds__(256) sinkhorn_colB(void)
{
    int i = blockIdx.x * 256 + threadIdx.x;
    if (i < BB*NP) {
        int b = i >> 11, m = i & (NP - 1);
        g_lv[i] = merge_lv(b, m);
    }
}

/* ------------ argmax over m of g_K[n][m] + lv[m]  (lu[n] const per row) ------------ */
__global__ void __launch_bounds__(256) assign_fast(void)
{
    __shared__ float shl[NP];
    int b = blockIdx.y;
    for (int i = threadIdx.x; i < NP; i += 256) shl[i] = g_lv[b*NP + i];
    __syncthreads();

    int warp = threadIdx.x >> 5, lane = threadIdx.x & 31;
    int row = blockIdx.x * 8 + warp;
    const float4* M4 = (const float4*)(g_K + ((size_t)b*NP + row) * NP);
    const float4* L4 = (const float4*)shl;

    float best = -CUDART_INF_F;
    int   bi = 0;
    for (int i = 0; i < NP/128; i++) {
        float4 k = M4[i*32 + lane];
        float4 l = L4[i*32 + lane];
        int m0 = (i*32 + lane) * 4;
        float v;
        v = __fadd_rn(k.x, l.x); if (v > best) { best = v; bi = m0;     }
        v = __fadd_rn(k.y, l.y); if (v > best) { best = v; bi = m0 + 1; }
        v = __fadd_rn(k.z, l.z); if (v > best) { best = v; bi = m0 + 2; }
        v = __fadd_rn(k.w, l.w); if (v > best) { best = v; bi = m0 + 3; }
    }
#pragma unroll
    for (int off = 16; off; off >>= 1) {
        float ov = __shfl_xor_sync(0xffffffffu, best, off);
        int   oi = __shfl_xor_sync(0xffffffffu, bi,   off);
        if (ov > best || (ov == best && oi < bi)) { best = ov; bi = oi; }
    }
    if (lane == 0) g_assign[b*NP + row] = bi;
}

/* ------------ KNN (exact sorted top-64 via bitonic) + masked loss ------------ */
__global__ void __launch_bounds__(256) knn_loss_kernel(
    const float* __restrict__ inputs,
    const float* __restrict__ preds)
{
    __shared__ unsigned long long keys[NP];
    __shared__ float redm[KNN], redw[KNN];
    __shared__ float sh_d63;

    int row = blockIdx.x;
    int b = row >> 11, n = row & (NP - 1);
    const float* inp = inputs + b*NP*3;
    float ax = tf32r(inp[3*n]), ay = tf32r(inp[3*n+1]), az = tf32r(inp[3*n+2]);
    float sa = g_sin[b*NP + n];

    for (int m = threadIdx.x; m < NP; m += 256) {
        float bx = tf32r(inp[3*m]), by = tf32r(inp[3*m+1]), bz = tf32r(inp[3*m+2]);
        float dot = fmaf(az, bz, fmaf(ay, by, ax * bx));
        float d2  = fmaxf(__fadd_rn(__fadd_rn(sa, g_sin[b*NP + m]), -2.0f * dot), 0.f);
        keys[m] = (((unsigned long long)__float_as_uint(d2)) << 32) | (unsigned)m;
    }
    __syncthreads();

    /* ascending bitonic sort: key = (d2_bits, idx) reproduces top_k stable ties */
    for (int k = 2; k <= NP; k <<= 1) {
        for (int j = k >> 1; j > 0; j >>= 1) {
            for (int i = threadIdx.x; i < NP; i += 256) {
                int ixj = i ^ j;
                if (ixj > i) {
                    unsigned long long x = keys[i], y = keys[ixj];
                    bool up = ((i & k) == 0);
                    if ((x > y) == up) { keys[i] = y; keys[ixj] = x; }
                }
            }
            __syncthreads();
        }
    }

    int tid = threadIdx.x;
    if (tid < KNN) {
        unsigned long long key = keys[tid + 1];   /* drop self (rank 0) */
        int   idx = (int)(key & 0xffffffffull);
        float d   = __uint_as_float((unsigned)(key >> 32));

        const float C1 = (float)(0.05 * 0.05);
        const float C2 = (float)(2.0 * 0.5657 * 0.5657);
        const float C3 = (float)(0.5657 * 2.5066282746);
        float prob = expf(-(d / C1) / C2) / C3;

        /* exact JAX uniform(key(42), (4,2048,64)) */
        unsigned lin = ((unsigned)row << 6) | (unsigned)tid;
        const unsigned H = (unsigned)(BB * NP * KNN / 2);   /* 262144 */
        unsigned x0, x1, bits;
        if (lin < H) { x0 = lin;     x1 = lin + H; threefry2x32(0u, 42u, x0, x1); bits = x0; }
        else         { x0 = lin - H; x1 = lin;     threefry2x32(0u, 42u, x0, x1); bits = x1; }
        float u = __uint_as_float((bits >> 9) | 0x3f800000u) - 1.0f;
        float mask = (u < prob) ? 1.0f : 0.0f;

        int pidx = g_assign[b*NP + n];
        const float* pp = preds + (b*NP + pidx)*3;
        const float* xp = inp + idx*3;
        float dx = pp[0] - xp[0], dy = pp[1] - xp[1], dz = pp[2] - xp[2];
        float dist = fmaf(dz, dz, fmaf(dy, dy, dx * dx));

        redm[tid] = mask;
        redw[tid] = mask * dist;
        if (tid == KNN - 1) sh_d63 = dist;
    }
    __syncthreads();

    if (tid == 0) {
        float ms = 0.f, ws = 0.f;
#pragma unroll
        for (int q = 0; q < KNN; q++) { ms += redm[q]; ws += redw[q]; }
        g_avg[row] = (ms == 0.f) ? sh_d63 : (ws / ms);
    }
}

/* ------------ deterministic final reduction ------------ */
__global__ void reduce_kernel(float* __restrict__ out)
{
    __shared__ float sh[256];
    float s = 0.f;
    for (int i = threadIdx.x; i < BB*NP; i += 256) s += g_avg[i];
    sh[threadIdx.x] = s;
    __syncthreads();
    for (int off = 128; off; off >>= 1) {
        if (threadIdx.x < off) sh[threadIdx.x] += sh[threadIdx.x + off];
        __syncthreads();
    }
    if (threadIdx.x == 0) out[0] = sh[0];
}

extern "C" void kernel_launch(void* const* d_in, const int* in_sizes, int n_in,
                              void* d_out, int out_size)
{
    const float* preds  = (const float*)d_in[0];
    const float* inputs = (const float*)d_in[1];

    init_kernel<<<(BB*NP + 255) / 256, 256>>>(preds, inputs);

    dim3 g(NP / 8, BB);
    dim3 gA(64 * NSEG, BB);
    build_logK<<<g, 256>>>(inputs, preds);      /* g_K[n][m] */

    sinkhorn_row<1><<<g,  256>>>();             /* it=0: lv = zeros */
    sinkhorn_colA  <<<gA, 256>>>();
    for (int it = 1; it < 50; ++it) {
        sinkhorn_row<0><<<g,  256>>>();         /* merges partials -> lv, then lu */
        sinkhorn_colA  <<<gA, 256>>>();
    }
    sinkhorn_colB<<<32, 256>>>();               /* final lv for assignment */
    assign_fast<<<g, 256>>>();
    knn_loss_kernel<<<BB*NP, 256>>>(inputs, preds);
    reduce_kernel<<<1, 256>>>((float*)d_out);
}

// round 14
// speedup vs baseline: 1.3562x; 1.3562x over previous
#include <cuda_runtime.h>
#include <math_constants.h>

#define BB   4
#define NP   2048
#define KNN  64
#define EPS  0.005f
#define LOG_MU (-7.6246190f)   /* -log(2048) */
#define NSEG 4                 /* row segments for the column pass */
#define NCAND 256              /* knn candidate capacity (est. need ~90) */

/* ------------ scratch (no allocations allowed) ------------ */
__device__ float g_lu[BB*NP];
__device__ float g_lv[BB*NP];
__device__ float g_sin[BB*NP];
__device__ float g_spr[BB*NP];
__device__ int   g_assign[BB*NP];
__device__ float g_avg[BB*NP];
__device__ float g_pmx[BB][NSEG][NP];   /* column-pass partial max  */
__device__ float g_psm[BB][NSEG][NP];   /* column-pass partial sum  */
/* materialized logK = -C/eps : [b][n][m] — 67 MB */
__device__ float g_K [(size_t)BB*NP*NP];

/* TF32 rounding (cuBLAS/CUTLASS conversion path: round-nearest-ties-away) */
__device__ __forceinline__ float tf32r(float x)
{
    float r;
    asm("cvt.rna.tf32.f32 %0, %1;" : "=f"(r) : "f"(x));
    return r;
}

/* online branchy logsumexp update (fast exp) */
#define ONL(e, mx, s) \
    { if ((e) > (mx)) { (s) = fmaf((s), __expf((mx) - (e)), 1.f); (mx) = (e); } \
      else              (s) += __expf((e) - (mx)); }

/* ------------ threefry2x32, bit-exact vs JAX ------------ */
__device__ __forceinline__ void threefry2x32(unsigned k0, unsigned k1,
                                             unsigned &x0, unsigned &x1)
{
    unsigned ks2 = k0 ^ k1 ^ 0x1BD11BDAu;
    x0 += k0; x1 += k1;
#define TFR(r) { x0 += x1; x1 = (x1 << (r)) | (x1 >> (32 - (r))); x1 ^= x0; }
    TFR(13) TFR(15) TFR(26) TFR(6)
    x0 += k1;  x1 += ks2 + 1u;
    TFR(17) TFR(29) TFR(16) TFR(24)
    x0 += ks2; x1 += k0 + 2u;
    TFR(13) TFR(15) TFR(26) TFR(6)
    x0 += k0;  x1 += k1 + 3u;
    TFR(17) TFR(29) TFR(16) TFR(24)
    x0 += k1;  x1 += ks2 + 4u;
    TFR(13) TFR(15) TFR(26) TFR(6)
    x0 += ks2; x1 += k0 + 5u;
#undef TFR
}

/* ------------ init: squared norms (full fp32) + zero duals ------------ */
__global__ void init_kernel(const float* __restrict__ preds,
                            const float* __restrict__ inputs)
{
    int i = blockIdx.x * blockDim.x + threadIdx.x;
    if (i < BB*NP) {
        float x = inputs[3*i], y = inputs[3*i+1], z = inputs[3*i+2];
        g_sin[i] = fmaf(z, z, fmaf(y, y, x*x));
        x = preds[3*i]; y = preds[3*i+1]; z = preds[3*i+2];
        g_spr[i] = fmaf(z, z, fmaf(y, y, x*x));
        g_lu[i] = 0.f;
        g_lv[i] = 0.f;
    }
}

/* ------------ build logK: g_K[b][n][m], rows = inputs, cols = preds ------------ */
__global__ void __launch_bounds__(256) build_logK(
    const float* __restrict__ rowPts,
    const float* __restrict__ innerPts)
{
    __shared__ float4 shp[NP];
    int b = blockIdx.y;
    const float* ip = innerPts + b*NP*3;
    for (int i = threadIdx.x; i < NP; i += 256)
        shp[i] = make_float4(tf32r(ip[3*i]), tf32r(ip[3*i+1]), tf32r(ip[3*i+2]),
                             g_spr[b*NP + i]);
    __syncthreads();

    int warp = threadIdx.x >> 5, lane = threadIdx.x & 31;
    int row = blockIdx.x * 8 + warp;
    const float* rp = rowPts + (b*NP + row)*3;
    float ax = tf32r(rp[0]), ay = tf32r(rp[1]), az = tf32r(rp[2]);
    float sa = g_sin[b*NP + row];
    float* orow = g_K + ((size_t)b*NP + row) * NP;

    for (int m = lane; m < NP; m += 32) {
        float4 p = shp[m];
        float dot = fmaf(az, p.z, fmaf(ay, p.y, ax * p.x));
        float d2  = fmaxf(__fadd_rn(__fadd_rn(sa, p.w), -2.0f * dot), 0.f);
        orow[m] = -(d2 / EPS);
    }
}

/* ------------ row half-step: lu[n] = LOG_MU - lse_m( g_K[n][m] + lv[m] ) ------------ */
__global__ void __launch_bounds__(256) sinkhorn_row(void)
{
    __shared__ float shl[NP];
    int b = blockIdx.y;
    for (int i = threadIdx.x; i < NP; i += 256) shl[i] = g_lv[b*NP + i];
    __syncthreads();

    int warp = threadIdx.x >> 5, lane = threadIdx.x & 31;
    int row = blockIdx.x * 8 + warp;
    const float4* M4 = (const float4*)(g_K + ((size_t)b*NP + row) * NP);
    const float4* L4 = (const float4*)shl;

    float mx0 = -CUDART_INF_F, mx1 = -CUDART_INF_F,
          mx2 = -CUDART_INF_F, mx3 = -CUDART_INF_F;
    float s0 = 0.f, s1 = 0.f, s2 = 0.f, s3 = 0.f;

#pragma unroll
    for (int ii = 0; ii < 16; ii += 4) {
        float4 k0 = M4[(ii+0)*32 + lane];
        float4 k1 = M4[(ii+1)*32 + lane];
        float4 k2 = M4[(ii+2)*32 + lane];
        float4 k3 = M4[(ii+3)*32 + lane];
        float4 l0 = L4[(ii+0)*32 + lane];
        float4 l1 = L4[(ii+1)*32 + lane];
        float4 l2 = L4[(ii+2)*32 + lane];
        float4 l3 = L4[(ii+3)*32 + lane];
        float e;
        e = __fadd_rn(k0.x, l0.x); ONL(e, mx0, s0)
        e = __fadd_rn(k0.y, l0.y); ONL(e, mx1, s1)
        e = __fadd_rn(k0.z, l0.z); ONL(e, mx2, s2)
        e = __fadd_rn(k0.w, l0.w); ONL(e, mx3, s3)
        e = __fadd_rn(k1.x, l1.x); ONL(e, mx0, s0)
        e = __fadd_rn(k1.y, l1.y); ONL(e, mx1, s1)
        e = __fadd_rn(k1.z, l1.z); ONL(e, mx2, s2)
        e = __fadd_rn(k1.w, l1.w); ONL(e, mx3, s3)
        e = __fadd_rn(k2.x, l2.x); ONL(e, mx0, s0)
        e = __fadd_rn(k2.y, l2.y); ONL(e, mx1, s1)
        e = __fadd_rn(k2.z, l2.z); ONL(e, mx2, s2)
        e = __fadd_rn(k2.w, l2.w); ONL(e, mx3, s3)
        e = __fadd_rn(k3.x, l3.x); ONL(e, mx0, s0)
        e = __fadd_rn(k3.y, l3.y); ONL(e, mx1, s1)
        e = __fadd_rn(k3.z, l3.z); ONL(e, mx2, s2)
        e = __fadd_rn(k3.w, l3.w); ONL(e, mx3, s3)
    }

    float nm, s, mx;
    nm = fmaxf(mx0, mx1); s0 = s0 * __expf(mx0 - nm) + s1 * __expf(mx1 - nm); mx0 = nm;
    nm = fmaxf(mx2, mx3); s2 = s2 * __expf(mx2 - nm) + s3 * __expf(mx3 - nm); mx2 = nm;
    nm = fmaxf(mx0, mx2); s  = s0 * __expf(mx0 - nm) + s2 * __expf(mx2 - nm); mx = nm;

#pragma unroll
    for (int off = 16; off; off >>= 1) {
        float om = __shfl_xor_sync(0xffffffffu, mx, off);
        float os = __shfl_xor_sync(0xffffffffu, s,  off);
        nm = fmaxf(mx, om);
        s  = s * __expf(mx - nm) + os * __expf(om - nm);
        mx = nm;
    }
    if (lane == 0) {
        float r = __fadd_rn(logf(s), mx);
        g_lu[b*NP + row] = __fadd_rn(LOG_MU, -r);
    }
}

/* ------------ column pass stage A: partial lse over a 32-col x 512-row tile ------------ */
__global__ void __launch_bounds__(256) sinkhorn_colA(void)
{
    __shared__ float shlu[512];
    __shared__ float smx[32][33], ssm[32][33];

    int b    = blockIdx.y;
    int seg  = blockIdx.x & (NSEG - 1);
    int tile = blockIdx.x >> 2;            /* 0..63 */
    int n0   = seg * 512;

    for (int i = threadIdx.x; i < 512; i += 256) shlu[i] = g_lu[b*NP + n0 + i];
    __syncthreads();

    int t = threadIdx.x;
    int u = t & 7, sg = t >> 3;
    int m0 = tile * 32;
    const float4* M4 = (const float4*)(g_K + (size_t)b*NP*NP + m0);

    float mxa = -CUDART_INF_F, mxb = -CUDART_INF_F,
          mxc = -CUDART_INF_F, mxd = -CUDART_INF_F;
    float sa = 0.f, sb = 0.f, sc = 0.f, sd = 0.f;

#pragma unroll
    for (int kk = 0; kk < 16; kk += 4) {
        int r0 = n0 + sg + 32*(kk+0);
        int r1 = n0 + sg + 32*(kk+1);
        int r2 = n0 + sg + 32*(kk+2);
        int r3 = n0 + sg + 32*(kk+3);
        float4 v0 = M4[(size_t)r0 * (NP/4) + u];
        float4 v1 = M4[(size_t)r1 * (NP/4) + u];
        float4 v2 = M4[(size_t)r2 * (NP/4) + u];
        float4 v3 = M4[(size_t)r3 * (NP/4) + u];
        float l0 = shlu[r0 - n0], l1 = shlu[r1 - n0],
              l2 = shlu[r2 - n0], l3 = shlu[r3 - n0];
        float e;
        e = __fadd_rn(v0.x, l0); ONL(e, mxa, sa)
        e = __fadd_rn(v0.y, l0); ONL(e, mxb, sb)
        e = __fadd_rn(v0.z, l0); ONL(e, mxc, sc)
        e = __fadd_rn(v0.w, l0); ONL(e, mxd, sd)
        e = __fadd_rn(v1.x, l1); ONL(e, mxa, sa)
        e = __fadd_rn(v1.y, l1); ONL(e, mxb, sb)
        e = __fadd_rn(v1.z, l1); ONL(e, mxc, sc)
        e = __fadd_rn(v1.w, l1); ONL(e, mxd, sd)
        e = __fadd_rn(v2.x, l2); ONL(e, mxa, sa)
        e = __fadd_rn(v2.y, l2); ONL(e, mxb, sb)
        e = __fadd_rn(v2.z, l2); ONL(e, mxc, sc)
        e = __fadd_rn(v2.w, l2); ONL(e, mxd, sd)
        e = __fadd_rn(v3.x, l3); ONL(e, mxa, sa)
        e = __fadd_rn(v3.y, l3); ONL(e, mxb, sb)
        e = __fadd_rn(v3.z, l3); ONL(e, mxc, sc)
        e = __fadd_rn(v3.w, l3); ONL(e, mxd, sd)
    }
    smx[sg][4*u+0] = mxa; ssm[sg][4*u+0] = sa;
    smx[sg][4*u+1] = mxb; ssm[sg][4*u+1] = sb;
    smx[sg][4*u+2] = mxc; ssm[sg][4*u+2] = sc;
    smx[sg][4*u+3] = mxd; ssm[sg][4*u+3] = sd;
    __syncthreads();

    if (t < 32) {
        float mx = -CUDART_INF_F, s = 0.f;
#pragma unroll
        for (int g = 0; g < 32; g++) {
            float m2 = smx[g][t], s2 = ssm[g][t];
            float nm = fmaxf(mx, m2);
            s = s * __expf(mx - nm) + s2 * __expf(m2 - nm);
            mx = nm;
        }
        g_pmx[b][seg][m0 + t] = mx;
        g_psm[b][seg][m0 + t] = s;
    }
}

/* ------------ column pass stage B: merge NSEG partials -> lv ------------ */
__global__ void __launch_bounds__(256) sinkhorn_colB(void)
{
    int i = blockIdx.x * 256 + threadIdx.x;
    if (i < BB*NP) {
        int b = i >> 11, m = i & (NP - 1);
        float mx = -CUDART_INF_F, s = 0.f;
#pragma unroll
        for (int seg = 0; seg < NSEG; seg++) {
            float m2 = g_pmx[b][seg][m], s2 = g_psm[b][seg][m];
            float nm = fmaxf(mx, m2);
            s = s * __expf(mx - nm) + s2 * __expf(m2 - nm);
            mx = nm;
        }
        float r = __fadd_rn(logf(s), mx);
        g_lv[i] = __fadd_rn(LOG_MU, -r);
    }
}

/* ------------ argmax over m of g_K[n][m] + lv[m]  (lu[n] const per row) ------------ */
__global__ void __launch_bounds__(256) assign_fast(void)
{
    __shared__ float shl[NP];
    int b = blockIdx.y;
    for (int i = threadIdx.x; i < NP; i += 256) shl[i] = g_lv[b*NP + i];
    __syncthreads();

    int warp = threadIdx.x >> 5, lane = threadIdx.x & 31;
    int row = blockIdx.x * 8 + warp;
    const float4* M4 = (const float4*)(g_K + ((size_t)b*NP + row) * NP);
    const float4* L4 = (const float4*)shl;

    float best = -CUDART_INF_F;
    int   bi = 0;
    for (int i = 0; i < NP/128; i++) {
        float4 k = M4[i*32 + lane];
        float4 l = L4[i*32 + lane];
        int m0 = (i*32 + lane) * 4;
        float v;
        v = __fadd_rn(k.x, l.x); if (v > best) { best = v; bi = m0;     }
        v = __fadd_rn(k.y, l.y); if (v > best) { best = v; bi = m0 + 1; }
        v = __fadd_rn(k.z, l.z); if (v > best) { best = v; bi = m0 + 2; }
        v = __fadd_rn(k.w, l.w); if (v > best) { best = v; bi = m0 + 3; }
    }
#pragma unroll
    for (int off = 16; off; off >>= 1) {
        float ov = __shfl_xor_sync(0xffffffffu, best, off);
        int   oi = __shfl_xor_sync(0xffffffffu, bi,   off);
        if (ov > best || (ov == best && oi < bi)) { best = ov; bi = oi; }
    }
    if (lane == 0) g_assign[b*NP + row] = bi;
}

/* ------------ KNN via histogram-select + small sort ------------
   1. keys[m] = (d2_bits << 32) | m  (same as full-sort version)
   2. 4096-bin histogram on d2_bits >> 19 (monotone for d2 >= 0)
   3. find bin B where cumulative count reaches 65
   4. collect all keys with bin <= B (superset of the 65 smallest)
   5. bitonic-sort NCAND candidates (identical comparator) -> ranks
      1..64 are bit-identical to the full sort's.                    */
__global__ void __launch_bounds__(256) knn_loss_kernel(
    const float* __restrict__ inputs,
    const float* __restrict__ preds)
{
    __shared__ unsigned long long keys[NP];      /* 16 KB */
    __shared__ int counts[4096];                 /* 16 KB */
    __shared__ int scan[256];
    __shared__ unsigned long long cand[NCAND];   /* 2 KB */
    __shared__ int ccnt, sh_B;
    __shared__ float redm[KNN], redw[KNN];
    __shared__ float sh_d63;

    int row = blockIdx.x;
    int b = row >> 11, n = row & (NP - 1);
    int tid = threadIdx.x;
    const float* inp = inputs + b*NP*3;
    float ax = tf32r(inp[3*n]), ay = tf32r(inp[3*n+1]), az = tf32r(inp[3*n+2]);
    float sa = g_sin[b*NP + n];

    for (int i = tid; i < 4096; i += 256) counts[i] = 0;
    if (tid == 0) ccnt = 0;
    __syncthreads();

    for (int m = tid; m < NP; m += 256) {
        float bx = tf32r(inp[3*m]), by = tf32r(inp[3*m+1]), bz = tf32r(inp[3*m+2]);
        float dot = fmaf(az, bz, fmaf(ay, by, ax * bx));
        float d2  = fmaxf(__fadd_rn(__fadd_rn(sa, g_sin[b*NP + m]), -2.0f * dot), 0.f);
        unsigned bits = __float_as_uint(d2);
        keys[m] = (((unsigned long long)bits) << 32) | (unsigned)m;
        atomicAdd(&counts[bits >> 19], 1);
    }
    __syncthreads();

    /* prefix over 256 thread-partials (16 bins each), find crossing bin */
    int base = tid * 16;
    int tsum = 0;
#pragma unroll
    for (int j = 0; j < 16; j++) tsum += counts[base + j];
    scan[tid] = tsum;
    __syncthreads();
    for (int off = 1; off < 256; off <<= 1) {
        int v = (tid >= off) ? scan[tid - off] : 0;
        __syncthreads();
        scan[tid] += v;
        __syncthreads();
    }
    int incl = scan[tid];
    int exc  = incl - tsum;
    if (exc < KNN + 1 && incl >= KNN + 1) {
        int c = exc;
#pragma unroll
        for (int j = 0; j < 16; j++) {
            c += counts[base + j];
            if (c >= KNN + 1) { sh_B = base + j; break; }
        }
    }
    __syncthreads();

    /* collect candidates: bin(key) = key >> 51 */
    int B = sh_B;
    for (int m = tid; m < NP; m += 256) {
        unsigned long long key = keys[m];
        if ((int)(key >> 51) <= B) {
            int pos = atomicAdd(&ccnt, 1);
            if (pos < NCAND) cand[pos] = key;
        }
    }
    __syncthreads();
    for (int i = ccnt + tid; i < NCAND; i += 256)
        cand[i] = 0xFFFFFFFFFFFFFFFFull;
    __syncthreads();

    /* bitonic sort NCAND (ascending) — same comparator as full sort */
    for (int k = 2; k <= NCAND; k <<= 1) {
        for (int j = k >> 1; j > 0; j >>= 1) {
            int i = tid;
            int ixj = i ^ j;
            if (ixj > i && i < NCAND) {
                unsigned long long x = cand[i], y = cand[ixj];
                bool up = ((i & k) == 0);
                if ((x > y) == up) { cand[i] = y; cand[ixj] = x; }
            }
            __syncthreads();
        }
    }

    if (tid < KNN) {
        unsigned long long key = cand[tid + 1];   /* drop self (rank 0) */
        int   idx = (int)(key & 0xffffffffull);
        float d   = __uint_as_float((unsigned)(key >> 32));

        const float C1 = (float)(0.05 * 0.05);
        const float C2 = (float)(2.0 * 0.5657 * 0.5657);
        const float C3 = (float)(0.5657 * 2.5066282746);
        float prob = expf(-(d / C1) / C2) / C3;

        /* exact JAX uniform(key(42), (4,2048,64)) */
        unsigned lin = ((unsigned)row << 6) | (unsigned)tid;
        const unsigned H = (unsigned)(BB * NP * KNN / 2);   /* 262144 */
        unsigned x0, x1, bits;
        if (lin < H) { x0 = lin;     x1 = lin + H; threefry2x32(0u, 42u, x0, x1); bits = x0; }
        else         { x0 = lin - H; x1 = lin;     threefry2x32(0u, 42u, x0, x1); bits = x1; }
        float u = __uint_as_float((bits >> 9) | 0x3f800000u) - 1.0f;
        float mask = (u < prob) ? 1.0f : 0.0f;

        int pidx = g_assign[b*NP + n];
        const float* pp = preds + (b*NP + pidx)*3;
        const float* xp = inp + idx*3;
        float dx = pp[0] - xp[0], dy = pp[1] - xp[1], dz = pp[2] - xp[2];
        float dist = fmaf(dz, dz, fmaf(dy, dy, dx * dx));

        redm[tid] = mask;
        redw[tid] = mask * dist;
        if (tid == KNN - 1) sh_d63 = dist;
    }
    __syncthreads();

    if (tid == 0) {
        float ms = 0.f, ws = 0.f;
#pragma unroll
        for (int q = 0; q < KNN; q++) { ms += redm[q]; ws += redw[q]; }
        g_avg[row] = (ms == 0.f) ? sh_d63 : (ws / ms);
    }
}

/* ------------ deterministic final reduction ------------ */
__global__ void reduce_kernel(float* __restrict__ out)
{
    __shared__ float sh[256];
    float s = 0.f;
    for (int i = threadIdx.x; i < BB*NP; i += 256) s += g_avg[i];
    sh[threadIdx.x] = s;
    __syncthreads();
    for (int off = 128; off; off >>= 1) {
        if (threadIdx.x < off) sh[threadIdx.x] += sh[threadIdx.x + off];
        __syncthreads();
    }
    if (threadIdx.x == 0) out[0] = sh[0];
}

extern "C" void kernel_launch(void* const* d_in, const int* in_sizes, int n_in,
                              void* d_out, int out_size)
{
    const float* preds  = (const float*)d_in[0];
    const float* inputs = (const float*)d_in[1];

    init_kernel<<<(BB*NP + 255) / 256, 256>>>(preds, inputs);

    dim3 g(NP / 8, BB);
    dim3 gA(64 * NSEG, BB);
    build_logK<<<g, 256>>>(inputs, preds);      /* g_K[n][m] */

    for (int it = 0; it < 50; ++it) {
        sinkhorn_row <<<g,  256>>>();   /* lu <- lse over rows  */
        sinkhorn_colA<<<gA, 256>>>();   /* column partials      */
        sinkhorn_colB<<<32, 256>>>();   /* merge -> lv          */
    }
    assign_fast<<<g, 256>>>();
    knn_loss_kernel<<<BB*NP, 256>>>(inputs, preds);
    reduce_kernel<<<1, 256>>>((float*)d_out);
}

// round 15
// speedup vs baseline: 1.9714x; 1.4537x over previous
#include <cuda_runtime.h>
#include <math_constants.h>

#define BB   4
#define NP   2048
#define KNN  64
#define EPS  0.005f
#define LOG_MU (-7.6246190f)   /* -log(2048) */
#define NSEG 4                 /* row segments for the column pass */
#define NCAND 256              /* knn candidate capacity (est. need ~90) */

/* ------------ scratch (no allocations allowed) ------------ */
__device__ float g_lu[BB*NP];
__device__ float g_lv[BB*NP];
__device__ float g_sin[BB*NP];
__device__ float g_spr[BB*NP];
__device__ int   g_assign[BB*NP];
__device__ float g_avg[BB*NP];
__device__ float g_pmx[BB][NSEG][NP];   /* column-pass partial max  */
__device__ float g_psm[BB][NSEG][NP];   /* column-pass partial sum  */
/* materialized logK = -C/eps : [b][n][m] — 67 MB */
__device__ float g_K [(size_t)BB*NP*NP];

/* TF32 rounding (cuBLAS/CUTLASS conversion path: round-nearest-ties-away) */
__device__ __forceinline__ float tf32r(float x)
{
    float r;
    asm("cvt.rna.tf32.f32 %0, %1;" : "=f"(r) : "f"(x));
    return r;
}

/* ------------ threefry2x32, bit-exact vs JAX ------------ */
__device__ __forceinline__ void threefry2x32(unsigned k0, unsigned k1,
                                             unsigned &x0, unsigned &x1)
{
    unsigned ks2 = k0 ^ k1 ^ 0x1BD11BDAu;
    x0 += k0; x1 += k1;
#define TFR(r) { x0 += x1; x1 = (x1 << (r)) | (x1 >> (32 - (r))); x1 ^= x0; }
    TFR(13) TFR(15) TFR(26) TFR(6)
    x0 += k1;  x1 += ks2 + 1u;
    TFR(17) TFR(29) TFR(16) TFR(24)
    x0 += ks2; x1 += k0 + 2u;
    TFR(13) TFR(15) TFR(26) TFR(6)
    x0 += k0;  x1 += k1 + 3u;
    TFR(17) TFR(29) TFR(16) TFR(24)
    x0 += k1;  x1 += ks2 + 4u;
    TFR(13) TFR(15) TFR(26) TFR(6)
    x0 += ks2; x1 += k0 + 5u;
#undef TFR
}

/* ------------ init: squared norms (full fp32) + zero duals ------------ */
__global__ void init_kernel(const float* __restrict__ preds,
                            const float* __restrict__ inputs)
{
    int i = blockIdx.x * blockDim.x + threadIdx.x;
    if (i < BB*NP) {
        float x = inputs[3*i], y = inputs[3*i+1], z = inputs[3*i+2];
        g_sin[i] = fmaf(z, z, fmaf(y, y, x*x));
        x = preds[3*i]; y = preds[3*i+1]; z = preds[3*i+2];
        g_spr[i] = fmaf(z, z, fmaf(y, y, x*x));
        g_lu[i] = 0.f;
        g_lv[i] = 0.f;
    }
}

/* ------------ build logK: g_K[b][n][m], rows = inputs, cols = preds ------------ */
__global__ void __launch_bounds__(256) build_logK(
    const float* __restrict__ rowPts,
    const float* __restrict__ innerPts)
{
    __shared__ float4 shp[NP];
    int b = blockIdx.y;
    const float* ip = innerPts + b*NP*3;
    for (int i = threadIdx.x; i < NP; i += 256)
        shp[i] = make_float4(tf32r(ip[3*i]), tf32r(ip[3*i+1]), tf32r(ip[3*i+2]),
                             g_spr[b*NP + i]);
    __syncthreads();

    int warp = threadIdx.x >> 5, lane = threadIdx.x & 31;
    int row = blockIdx.x * 8 + warp;
    const float* rp = rowPts + (b*NP + row)*3;
    float ax = tf32r(rp[0]), ay = tf32r(rp[1]), az = tf32r(rp[2]);
    float sa = g_sin[b*NP + row];
    float* orow = g_K + ((size_t)b*NP + row) * NP;

    for (int m = lane; m < NP; m += 32) {
        float4 p = shp[m];
        float dot = fmaf(az, p.z, fmaf(ay, p.y, ax * p.x));
        float d2  = fmaxf(__fadd_rn(__fadd_rn(sa, p.w), -2.0f * dot), 0.f);
        orow[m] = -(d2 / EPS);
    }
}

/* merge NSEG column partials for column m -> lv value (colB algebra) */
__device__ __forceinline__ float merge_lv(int b, int m)
{
    float mx = -CUDART_INF_F, s = 0.f;
#pragma unroll
    for (int seg = 0; seg < NSEG; seg++) {
        float m2 = g_pmx[b][seg][m], s2 = g_psm[b][seg][m];
        float nm = fmaxf(mx, m2);
        s = s * __expf(mx - nm) + s2 * __expf(m2 - nm);
        mx = nm;
    }
    float r = __fadd_rn(logf(s), mx);
    return __fadd_rn(LOG_MU, -r);
}

/* ------------ row half-step (fused lv merge, chunk-max lse):
   lu[n] = LOG_MU - lse_m( g_K[n][m] + lv[m] )
   FIRST=1: lv read from g_lv (zeros); FIRST=0: lv merged from partials.
   Per 16-elem chunk: FMAX chain for chunk max, one rescale, fixed-shift
   __expf sums (exponents always <= 0 — per-row robustness preserved).   */
template<int FIRST>
__global__ void __launch_bounds__(256) sinkhorn_row(void)
{
    __shared__ float shl[NP];
    int b = blockIdx.y;
    if (FIRST) {
        for (int i = threadIdx.x; i < NP; i += 256) shl[i] = g_lv[b*NP + i];
    } else {
        for (int i = threadIdx.x; i < NP; i += 256) shl[i] = merge_lv(b, i);
    }
    __syncthreads();

    int warp = threadIdx.x >> 5, lane = threadIdx.x & 31;
    int row = blockIdx.x * 8 + warp;
    const float4* M4 = (const float4*)(g_K + ((size_t)b*NP + row) * NP);
    const float4* L4 = (const float4*)shl;

    float mx = -CUDART_INF_F;
    float s0 = 0.f, s1 = 0.f, s2 = 0.f, s3 = 0.f;

#pragma unroll
    for (int ii = 0; ii < 16; ii += 4) {
        float4 k0 = M4[(ii+0)*32 + lane];
        float4 k1 = M4[(ii+1)*32 + lane];
        float4 k2 = M4[(ii+2)*32 + lane];
        float4 k3 = M4[(ii+3)*32 + lane];
        float4 l0 = L4[(ii+0)*32 + lane];
        float4 l1 = L4[(ii+1)*32 + lane];
        float4 l2 = L4[(ii+2)*32 + lane];
        float4 l3 = L4[(ii+3)*32 + lane];
        float e00 = __fadd_rn(k0.x, l0.x), e01 = __fadd_rn(k0.y, l0.y);
        float e02 = __fadd_rn(k0.z, l0.z), e03 = __fadd_rn(k0.w, l0.w);
        float e10 = __fadd_rn(k1.x, l1.x), e11 = __fadd_rn(k1.y, l1.y);
        float e12 = __fadd_rn(k1.z, l1.z), e13 = __fadd_rn(k1.w, l1.w);
        float e20 = __fadd_rn(k2.x, l2.x), e21 = __fadd_rn(k2.y, l2.y);
        float e22 = __fadd_rn(k2.z, l2.z), e23 = __fadd_rn(k2.w, l2.w);
        float e30 = __fadd_rn(k3.x, l3.x), e31 = __fadd_rn(k3.y, l3.y);
        float e32 = __fadd_rn(k3.z, l3.z), e33 = __fadd_rn(k3.w, l3.w);

        float cm = fmaxf(fmaxf(fmaxf(e00, e01), fmaxf(e02, e03)),
                         fmaxf(fmaxf(e10, e11), fmaxf(e12, e13)));
        cm = fmaxf(cm, fmaxf(fmaxf(fmaxf(e20, e21), fmaxf(e22, e23)),
                             fmaxf(fmaxf(e30, e31), fmaxf(e32, e33))));
        if (cm > mx) {
            float r = __expf(mx - cm);
            s0 *= r; s1 *= r; s2 *= r; s3 *= r;
            mx = cm;
        }
        s0 += __expf(e00 - mx) + __expf(e10 - mx)
            + __expf(e20 - mx) + __expf(e30 - mx);
        s1 += __expf(e01 - mx) + __expf(e11 - mx)
            + __expf(e21 - mx) + __expf(e31 - mx);
        s2 += __expf(e02 - mx) + __expf(e12 - mx)
            + __expf(e22 - mx) + __expf(e32 - mx);
        s3 += __expf(e03 - mx) + __expf(e13 - mx)
            + __expf(e23 - mx) + __expf(e33 - mx);
    }

    float s = __fadd_rn(__fadd_rn(s0, s1), __fadd_rn(s2, s3));
#pragma unroll
    for (int off = 16; off; off >>= 1) {
        float om = __shfl_xor_sync(0xffffffffu, mx, off);
        float os = __shfl_xor_sync(0xffffffffu, s,  off);
        float nm = fmaxf(mx, om);
        s  = s * __expf(mx - nm) + os * __expf(om - nm);
        mx = nm;
    }
    if (lane == 0) {
        float r = __fadd_rn(logf(s), mx);
        g_lu[b*NP + row] = __fadd_rn(LOG_MU, -r);
    }
}

/* ------------ column pass stage A: partial lse over a 32-col x 512-row tile.
   Chunk-max lse per column (4 rows per chunk).                           */
__global__ void __launch_bounds__(256) sinkhorn_colA(void)
{
    __shared__ float shlu[512];
    __shared__ float smx[32][33], ssm[32][33];

    int b    = blockIdx.y;
    int seg  = blockIdx.x & (NSEG - 1);
    int tile = blockIdx.x >> 2;            /* 0..63 */
    int n0   = seg * 512;

    for (int i = threadIdx.x; i < 512; i += 256) shlu[i] = g_lu[b*NP + n0 + i];
    __syncthreads();

    int t = threadIdx.x;
    int u = t & 7, sg = t >> 3;
    int m0 = tile * 32;
    const float4* M4 = (const float4*)(g_K + (size_t)b*NP*NP + m0);

    float mxa = -CUDART_INF_F, mxb = -CUDART_INF_F,
          mxc = -CUDART_INF_F, mxd = -CUDART_INF_F;
    float sa = 0.f, sb = 0.f, sc = 0.f, sd = 0.f;

#pragma unroll
    for (int kk = 0; kk < 16; kk += 4) {
        int r0 = n0 + sg + 32*(kk+0);
        int r1 = n0 + sg + 32*(kk+1);
        int r2 = n0 + sg + 32*(kk+2);
        int r3 = n0 + sg + 32*(kk+3);
        float4 v0 = M4[(size_t)r0 * (NP/4) + u];
        float4 v1 = M4[(size_t)r1 * (NP/4) + u];
        float4 v2 = M4[(size_t)r2 * (NP/4) + u];
        float4 v3 = M4[(size_t)r3 * (NP/4) + u];
        float l0 = shlu[r0 - n0], l1 = shlu[r1 - n0],
              l2 = shlu[r2 - n0], l3 = shlu[r3 - n0];

        float ea0 = __fadd_rn(v0.x, l0), ea1 = __fadd_rn(v1.x, l1);
        float ea2 = __fadd_rn(v2.x, l2), ea3 = __fadd_rn(v3.x, l3);
        float cm = fmaxf(fmaxf(ea0, ea1), fmaxf(ea2, ea3));
        if (cm > mxa) { sa *= __expf(mxa - cm); mxa = cm; }
        sa += __expf(ea0 - mxa) + __expf(ea1 - mxa)
            + __expf(ea2 - mxa) + __expf(ea3 - mxa);

        float eb0 = __fadd_rn(v0.y, l0), eb1 = __fadd_rn(v1.y, l1);
        float eb2 = __fadd_rn(v2.y, l2), eb3 = __fadd_rn(v3.y, l3);
        cm = fmaxf(fmaxf(eb0, eb1), fmaxf(eb2, eb3));
        if (cm > mxb) { sb *= __expf(mxb - cm); mxb = cm; }
        sb += __expf(eb0 - mxb) + __expf(eb1 - mxb)
            + __expf(eb2 - mxb) + __expf(eb3 - mxb);

        float ec0 = __fadd_rn(v0.z, l0), ec1 = __fadd_rn(v1.z, l1);
        float ec2 = __fadd_rn(v2.z, l2), ec3 = __fadd_rn(v3.z, l3);
        cm = fmaxf(fmaxf(ec0, ec1), fmaxf(ec2, ec3));
        if (cm > mxc) { sc *= __expf(mxc - cm); mxc = cm; }
        sc += __expf(ec0 - mxc) + __expf(ec1 - mxc)
            + __expf(ec2 - mxc) + __expf(ec3 - mxc);

        float ed0 = __fadd_rn(v0.w, l0), ed1 = __fadd_rn(v1.w, l1);
        float ed2 = __fadd_rn(v2.w, l2), ed3 = __fadd_rn(v3.w, l3);
        cm = fmaxf(fmaxf(ed0, ed1), fmaxf(ed2, ed3));
        if (cm > mxd) { sd *= __expf(mxd - cm); mxd = cm; }
        sd += __expf(ed0 - mxd) + __expf(ed1 - mxd)
            + __expf(ed2 - mxd) + __expf(ed3 - mxd);
    }
    smx[sg][4*u+0] = mxa; ssm[sg][4*u+0] = sa;
    smx[sg][4*u+1] = mxb; ssm[sg][4*u+1] = sb;
    smx[sg][4*u+2] = mxc; ssm[sg][4*u+2] = sc;
    smx[sg][4*u+3] = mxd; ssm[sg][4*u+3] = sd;
    __syncthreads();

    if (t < 32) {
        float mx = -CUDART_INF_F, s = 0.f;
#pragma unroll
        for (int g = 0; g < 32; g++) {
            float m2 = smx[g][t], s2 = ssm[g][t];
            float nm = fmaxf(mx, m2);
            s = s * __expf(mx - nm) + s2 * __expf(m2 - nm);
            mx = nm;
        }
        g_pmx[b][seg][m0 + t] = mx;
        g_psm[b][seg][m0 + t] = s;
    }
}

/* ------------ column pass stage B (once, before assign): merge -> g_lv ------------ */
__global__ void __launch_bounds__(256) sinkhorn_colB(void)
{
    int i = blockIdx.x * 256 + threadIdx.x;
    if (i < BB*NP) {
        int b = i >> 11, m = i & (NP - 1);
        g_lv[i] = merge_lv(b, m);
    }
}

/* ------------ argmax over m of g_K[n][m] + lv[m]  (lu[n] const per row) ------------ */
__global__ void __launch_bounds__(256) assign_fast(void)
{
    __shared__ float shl[NP];
    int b = blockIdx.y;
    for (int i = threadIdx.x; i < NP; i += 256) shl[i] = g_lv[b*NP + i];
    __syncthreads();

    int warp = threadIdx.x >> 5, lane = threadIdx.x & 31;
    int row = blockIdx.x * 8 + warp;
    const float4* M4 = (const float4*)(g_K + ((size_t)b*NP + row) * NP);
    const float4* L4 = (const float4*)shl;

    float best = -CUDART_INF_F;
    int   bi = 0;
    for (int i = 0; i < NP/128; i++) {
        float4 k = M4[i*32 + lane];
        float4 l = L4[i*32 + lane];
        int m0 = (i*32 + lane) * 4;
        float v;
        v = __fadd_rn(k.x, l.x); if (v > best) { best = v; bi = m0;     }
        v = __fadd_rn(k.y, l.y); if (v > best) { best = v; bi = m0 + 1; }
        v = __fadd_rn(k.z, l.z); if (v > best) { best = v; bi = m0 + 2; }
        v = __fadd_rn(k.w, l.w); if (v > best) { best = v; bi = m0 + 3; }
    }
#pragma unroll
    for (int off = 16; off; off >>= 1) {
        float ov = __shfl_xor_sync(0xffffffffu, best, off);
        int   oi = __shfl_xor_sync(0xffffffffu, bi,   off);
        if (ov > best || (ov == best && oi < bi)) { best = ov; bi = oi; }
    }
    if (lane == 0) g_assign[b*NP + row] = bi;
}

/* ------------ KNN via histogram-select + small sort (bit-identical ranks) ------------ */
__global__ void __launch_bounds__(256) knn_loss_kernel(
    const float* __restrict__ inputs,
    const float* __restrict__ preds)
{
    __shared__ unsigned long long keys[NP];      /* 16 KB */
    __shared__ int counts[4096];                 /* 16 KB */
    __shared__ int scan[256];
    __shared__ unsigned long long cand[NCAND];   /* 2 KB */
    __shared__ int ccnt, sh_B;
    __shared__ float redm[KNN], redw[KNN];
    __shared__ float sh_d63;

    int row = blockIdx.x;
    int b = row >> 11, n = row & (NP - 1);
    int tid = threadIdx.x;
    const float* inp = inputs + b*NP*3;
    float ax = tf32r(inp[3*n]), ay = tf32r(inp[3*n+1]), az = tf32r(inp[3*n+2]);
    float sa = g_sin[b*NP + n];

    for (int i = tid; i < 4096; i += 256) counts[i] = 0;
    if (tid == 0) ccnt = 0;
    __syncthreads();

    for (int m = tid; m < NP; m += 256) {
        float bx = tf32r(inp[3*m]), by = tf32r(inp[3*m+1]), bz = tf32r(inp[3*m+2]);
        float dot = fmaf(az, bz, fmaf(ay, by, ax * bx));
        float d2  = fmaxf(__fadd_rn(__fadd_rn(sa, g_sin[b*NP + m]), -2.0f * dot), 0.f);
        unsigned bits = __float_as_uint(d2);
        keys[m] = (((unsigned long long)bits) << 32) | (unsigned)m;
        atomicAdd(&counts[bits >> 19], 1);
    }
    __syncthreads();

    int base = tid * 16;
    int tsum = 0;
#pragma unroll
    for (int j = 0; j < 16; j++) tsum += counts[base + j];
    scan[tid] = tsum;
    __syncthreads();
    for (int off = 1; off < 256; off <<= 1) {
        int v = (tid >= off) ? scan[tid - off] : 0;
        __syncthreads();
        scan[tid] += v;
        __syncthreads();
    }
    int incl = scan[tid];
    int exc  = incl - tsum;
    if (exc < KNN + 1 && incl >= KNN + 1) {
        int c = exc;
#pragma unroll
        for (int j = 0; j < 16; j++) {
            c += counts[base + j];
            if (c >= KNN + 1) { sh_B = base + j; break; }
        }
    }
    __syncthreads();

    int B = sh_B;
    for (int m = tid; m < NP; m += 256) {
        unsigned long long key = keys[m];
        if ((int)(key >> 51) <= B) {
            int pos = atomicAdd(&ccnt, 1);
            if (pos < NCAND) cand[pos] = key;
        }
    }
    __syncthreads();
    for (int i = ccnt + tid; i < NCAND; i += 256)
        cand[i] = 0xFFFFFFFFFFFFFFFFull;
    __syncthreads();

    for (int k = 2; k <= NCAND; k <<= 1) {
        for (int j = k >> 1; j > 0; j >>= 1) {
            int i = tid;
            int ixj = i ^ j;
            if (ixj > i && i < NCAND) {
                unsigned long long x = cand[i], y = cand[ixj];
                bool up = ((i & k) == 0);
                if ((x > y) == up) { cand[i] = y; cand[ixj] = x; }
            }
            __syncthreads();
        }
    }

    if (tid < KNN) {
        unsigned long long key = cand[tid + 1];   /* drop self (rank 0) */
        int   idx = (int)(key & 0xffffffffull);
        float d   = __uint_as_float((unsigned)(key >> 32));

        const float C1 = (float)(0.05 * 0.05);
        const float C2 = (float)(2.0 * 0.5657 * 0.5657);
        const float C3 = (float)(0.5657 * 2.5066282746);
        float prob = expf(-(d / C1) / C2) / C3;

        unsigned lin = ((unsigned)row << 6) | (unsigned)tid;
        const unsigned H = (unsigned)(BB * NP * KNN / 2);   /* 262144 */
        unsigned x0, x1, bits;
        if (lin < H) { x0 = lin;     x1 = lin + H; threefry2x32(0u, 42u, x0, x1); bits = x0; }
        else         { x0 = lin - H; x1 = lin;     threefry2x32(0u, 42u, x0, x1); bits = x1; }
        float u = __uint_as_float((bits >> 9) | 0x3f800000u) - 1.0f;
        float mask = (u < prob) ? 1.0f : 0.0f;

        int pidx = g_assign[b*NP + n];
        const float* pp = preds + (b*NP + pidx)*3;
        const float* xp = inp + idx*3;
        float dx = pp[0] - xp[0], dy = pp[1] - xp[1], dz = pp[2] - xp[2];
        float dist = fmaf(dz, dz, fmaf(dy, dy, dx * dx));

        redm[tid] = mask;
        redw[tid] = mask * dist;
        if (tid == KNN - 1) sh_d63 = dist;
    }
    __syncthreads();

    if (tid == 0) {
        float ms = 0.f, ws = 0.f;
#pragma unroll
        for (int q = 0; q < KNN; q++) { ms += redm[q]; ws += redw[q]; }
        g_avg[row] = (ms == 0.f) ? sh_d63 : (ws / ms);
    }
}

/* ------------ deterministic final reduction ------------ */
__global__ void reduce_kernel(float* __restrict__ out)
{
    __shared__ float sh[256];
    float s = 0.f;
    for (int i = threadIdx.x; i < BB*NP; i += 256) s += g_avg[i];
    sh[threadIdx.x] = s;
    __syncthreads();
    for (int off = 128; off; off >>= 1) {
        if (threadIdx.x < off) sh[threadIdx.x] += sh[threadIdx.x + off];
        __syncthreads();
    }
    if (threadIdx.x == 0) out[0] = sh[0];
}

extern "C" void kernel_launch(void* const* d_in, const int* in_sizes, int n_in,
                              void* d_out, int out_size)
{
    const float* preds  = (const float*)d_in[0];
    const float* inputs = (const float*)d_in[1];

    init_kernel<<<(BB*NP + 255) / 256, 256>>>(preds, inputs);

    dim3 g(NP / 8, BB);
    dim3 gA(64 * NSEG, BB);
    build_logK<<<g, 256>>>(inputs, preds);      /* g_K[n][m] */

    sinkhorn_row<1><<<g,  256>>>();             /* it=0: lv = zeros */
    sinkhorn_colA  <<<gA, 256>>>();
    for (int it = 1; it < 50; ++it) {
        sinkhorn_row<0><<<g,  256>>>();         /* merge partials -> lv, then lu */
        sinkhorn_colA  <<<gA, 256>>>();
    }
    sinkhorn_colB<<<32, 256>>>();               /* final lv for assignment */
    assign_fast<<<g, 256>>>();
    knn_loss_kernel<<<BB*NP, 256>>>(inputs, preds);
    reduce_kernel<<<1, 256>>>((float*)d_out);
}